// round 15
// baseline (speedup 1.0000x reference)
#include <cuda_runtime.h>
#include <cuda_fp16.h>
#include <cstdint>
#include <cstddef>

#define B_   128
#define S_   1024
#define IN_  256
#define H_   1024
#define G4_  4096
#define OUT_ 256
#define NC_  128     // CTAs (1/SM): (bh 2) x (jgrp 64)
#define GRP_ 64      // CTAs per batch-half group
#define NW_  16      // compute warps per CTA
#define ARR_ (GRP_*NW_) // warp arrivals per group per step (1024)
#define NSTG 4       // A pipeline stages (16KB each = 2 chunks)
#define CHB  8192    // chunk: 64 rows x 64 cols fp16, SW128 image
#define STGB 16384   // stage bytes (2 chunks)

// ---------------- device globals -------------------------------------------
__device__ __align__(1024) char g_x [(size_t)S_*2*4*CHB];   // 64 MB
__device__ __align__(1024) char g_h [2][2][16*CHB];          // 512 KB
__device__ __align__(16)  __half g_WxT[(size_t)G4_*IN_];     // [n][k]
__device__ __align__(16)  __half g_WhT[(size_t)G4_*H_];      // [n][k]
__device__ unsigned g_cnt[2];       // per-group warp-arrival counters

__device__ __host__ __forceinline__ int swz(int o){ return o ^ ((o >> 3) & 0x70); }

// ---------------- helpers ---------------------------------------------------
__device__ __forceinline__ void cp16(void* smem, const void* gmem){
    unsigned s = (unsigned)__cvta_generic_to_shared(smem);
    asm volatile("cp.async.cg.shared.global [%0], [%1], 16;\n" :: "r"(s), "l"(gmem));
}
__device__ __forceinline__ void cp_commit(){ asm volatile("cp.async.commit_group;\n"); }
template<int N> __device__ __forceinline__ void cp_wait(){ asm volatile("cp.async.wait_group %0;\n" :: "n"(N)); }

__device__ __forceinline__ void mbar_init(uint32_t mbar, uint32_t cnt){
    asm volatile("mbarrier.init.shared.b64 [%0], %1;\n" :: "r"(mbar), "r"(cnt) : "memory");
}
__device__ __forceinline__ void mbar_expect_tx(uint32_t mbar, uint32_t tx){
    asm volatile("mbarrier.arrive.expect_tx.shared.b64 _, [%0], %1;\n" :: "r"(mbar), "r"(tx) : "memory");
}
__device__ __forceinline__ void mbar_arrive(uint32_t mbar){
    asm volatile("mbarrier.arrive.shared.b64 _, [%0];\n" :: "r"(mbar) : "memory");
}
__device__ __forceinline__ void bulk_g2s(uint32_t sdst, const void* gsrc, uint32_t bytes, uint32_t mbar){
    asm volatile("cp.async.bulk.shared::cluster.global.mbarrier::complete_tx::bytes [%0], [%1], %2, [%3];\n"
                 :: "r"(sdst), "l"(gsrc), "r"(bytes), "r"(mbar) : "memory");
}
__device__ __forceinline__ void mbar_wait(uint32_t mbar, uint32_t parity){
    asm volatile(
        "{\n\t.reg .pred P1;\n\t"
        "LAB_W_%=:\n\t"
        "mbarrier.try_wait.parity.acquire.cta.shared::cta.b64 P1, [%0], %1;\n\t"
        "@P1 bra LAB_D_%=;\n\t"
        "bra LAB_W_%=;\n\t"
        "LAB_D_%=:\n\t}"
        :: "r"(mbar), "r"(parity) : "memory");
}
__device__ __forceinline__ void mma16816(float* c, uint32_t a0, uint32_t a1, uint32_t a2, uint32_t a3,
                                         uint32_t b0, uint32_t b1){
    asm volatile(
        "mma.sync.aligned.m16n8k16.row.col.f32.f16.f16.f32 "
        "{%0,%1,%2,%3}, {%4,%5,%6,%7}, {%8,%9}, {%0,%1,%2,%3};\n"
        : "+f"(c[0]), "+f"(c[1]), "+f"(c[2]), "+f"(c[3])
        : "r"(a0), "r"(a1), "r"(a2), "r"(a3), "r"(b0), "r"(b1));
}
__device__ __forceinline__ void ldsm4(uint32_t& r0, uint32_t& r1, uint32_t& r2, uint32_t& r3, uint32_t addr){
    asm volatile("ldmatrix.sync.aligned.m8n8.x4.shared.b16 {%0,%1,%2,%3}, [%4];\n"
                 : "=r"(r0), "=r"(r1), "=r"(r2), "=r"(r3) : "r"(addr));
}
__device__ __forceinline__ float sigm_(float x){ return 1.f / (1.f + __expf(-x)); }
__device__ __forceinline__ float tanh_(float x){ return 2.f / (1.f + __expf(-2.f*x)) - 1.f; }

// ---------------- phase 0: converts ----------------------------------------
__global__ void conv_x_kernel(const float* __restrict__ x){
    size_t n = (size_t)B_*S_*IN_;
    for (size_t i = (size_t)blockIdx.x*blockDim.x + threadIdx.x; i < n; i += (size_t)gridDim.x*blockDim.x){
        int k  = (int)(i % IN_);
        size_t bs = i / IN_;
        int s  = (int)(bs % S_);
        int b  = (int)(bs / S_);
        int bh = b >> 6, row = b & 63;
        char* chunk = g_x + (((size_t)s*2 + bh)*4 + (k >> 6))*CHB;
        *(__half*)(chunk + swz(row*128 + (k & 63)*2)) = __float2half(x[i]);
    }
}
__global__ void conv_w_kernel(const float* __restrict__ Wx, const float* __restrict__ Wh){
    size_t n1 = (size_t)G4_*IN_, n2 = (size_t)G4_*H_;
    for (size_t i = (size_t)blockIdx.x*blockDim.x + threadIdx.x; i < n1 + n2; i += (size_t)gridDim.x*blockDim.x){
        if (i < n1){
            int n = (int)(i / IN_), k = (int)(i % IN_);
            g_WxT[i] = __float2half(Wx[(size_t)k*G4_ + n]);
        } else {
            size_t j = i - n1;
            int n = (int)(j / H_), k = (int)(j % H_);
            g_WhT[j] = __float2half(Wh[(size_t)k*G4_ + n]);
        }
    }
}
__global__ void zero_h_kernel(){
    size_t n = sizeof(g_h)/4;
    unsigned* p = (unsigned*)g_h;
    for (size_t i = (size_t)blockIdx.x*blockDim.x + threadIdx.x; i < n; i += (size_t)gridDim.x*blockDim.x)
        p[i] = 0u;
    if (blockIdx.x == 0 && threadIdx.x < 2) g_cnt[threadIdx.x] = 0u;
}

// ---------------- recurrence ------------------------------------------------
// CTA (bh, jgrp): batch rows [bh*64,+64), hidden units [jgrp*16,+16) = 64 gate
// cols (col = hid*4+gate). SIXTEEN fully-decoupled compute warps, warp grid
// 4(wm) x 4(wn), tile 16x16 (1 A-ldsm + 1 B-ldsm + 2 HMMA per kk-slice).
// Producer warp streams 16KB bulk stages through a 4-stage mbarrier ring.
// No block syncs in the loop; warp-level global arrivals.
constexpr int A_OFF   = 0;
constexpr int WH_OFF  = NSTG*STGB;                // 65536
constexpr int WX_OFF  = WH_OFF + 16*CHB;          // 196608
constexpr int MB_OFF  = WX_OFF + 4*CHB;           // 229376
constexpr int SMEM_REC = MB_OFF + 2*NSTG*8 + 16;  // 229456

__global__ __launch_bounds__(544,1) void lstm_rec_kernel(const float* __restrict__ bias){
    extern __shared__ __align__(16) char sh[];
    int tid = threadIdx.x, lane = tid & 31, w = tid >> 5;
    int gid = lane >> 2, ctid = lane & 3;
    int bh = blockIdx.x & 1, jgrp = blockIdx.x >> 1;
    int j0 = jgrp * 16;
    int r0 = jgrp & 14;                         // rotated (even) h-chunk start

    uint32_t a_smem  = (uint32_t)__cvta_generic_to_shared(sh + A_OFF);
    uint32_t wh_smem = (uint32_t)__cvta_generic_to_shared(sh + WH_OFF);
    uint32_t wx_smem = (uint32_t)__cvta_generic_to_shared(sh + WX_OFF);
    uint32_t mb_full = (uint32_t)__cvta_generic_to_shared(sh + MB_OFF);   // +8*i
    uint32_t mb_emp  = mb_full + NSTG*8;                                  // +8*i
    char* Whs = sh + WH_OFF;
    char* Wxs = sh + WX_OFF;

    if (tid == 0){
        for (int i = 0; i < NSTG; i++){ mbar_init(mb_full + i*8, 1); mbar_init(mb_emp + i*8, NW_); }
        asm volatile("fence.proxy.async.shared::cta;\n" ::: "memory");
    }
    // weight slices into swizzled chunk format (row n = hid*4+gate, 64 rows)
    for (int idx = tid; idx < 64*128; idx += 544){
        int n = idx >> 7, u = idx & 127;
        int hid = n >> 2, g = n & 3, k = u*8;
        cp16(Whs + (k >> 6)*CHB + swz(n*128 + (k & 63)*2),
             g_WhT + ((size_t)(g*H_ + j0 + hid))*H_ + k);
    }
    for (int idx = tid; idx < 64*32; idx += 544){
        int n = idx >> 5, u = idx & 31;
        int hid = n >> 2, g = n & 3, k = u*8;
        cp16(Wxs + (k >> 6)*CHB + swz(n*128 + (k & 63)*2),
             g_WxT + ((size_t)(g*H_ + j0 + hid))*IN_ + k);
    }
    cp_commit(); cp_wait<0>();
    __syncthreads();   // the ONLY full-block sync

    if (w == NW_){
        // ----------------- producer warp (lane 0 only) -----------------
        if (lane == 0){
            int pst = 0, pwrap = 0;
            auto issue = [&](const char* src){
                if (pwrap > 0) mbar_wait(mb_emp + pst*8, (unsigned)((pwrap - 1) & 1));
                mbar_expect_tx(mb_full + pst*8, STGB);
                bulk_g2s(a_smem + pst*STGB, src, STGB, mb_full + pst*8);
                if (++pst == NSTG){ pst = 0; pwrap++; }
            };
            // x of t=0: 2 stages (32KB contiguous)
            issue(g_x + ((size_t)bh)*4*CHB);
            issue(g_x + ((size_t)bh)*4*CHB + STGB);
            for (int t = 0; t < S_; t++){
                if (t > 0){
                    unsigned v, tgtv = (unsigned)t * ARR_;
                    do { asm volatile("ld.acquire.gpu.global.u32 %0, [%1];\n" : "=r"(v) : "l"(&g_cnt[bh]) : "memory"); }
                    while (v < tgtv);
                }
                // h: 8 stages of 2 chunks, rotated even-aligned pairs (contiguous)
                for (int i = 0; i < 8; i++){
                    int ca = (r0 + 2*i) & 15;
                    issue(g_h[t & 1][bh] + ca*CHB);
                }
                if (t + 1 < S_){
                    const char* xb = g_x + (((size_t)(t+1)*2 + bh)*4)*CHB;
                    issue(xb);
                    issue(xb + STGB);
                }
            }
        }
        return;
    }

    // ----------------- compute warps (w = 0..15, tile 16x16, decoupled) ----
    int wm = w >> 2, wn = w & 3;               // warp tile: rows wm*16+, cols wn*16+

    // ldmatrix per-lane geometry
    int mat = lane >> 3, rin = lane & 7;
    uint32_t xorv = (uint32_t)(rin << 4);
    uint32_t ac   = (uint32_t)((mat >> 1) << 4);
    uint32_t arow = (uint32_t)((wm*16 + (mat & 1)*8 + rin) * 128);
    uint32_t brow = (uint32_t)((wn*16 + (mat & 1)*8 + rin) * 128);

    int odd = ctid & 1;
    // bias per (nt, gate); hid = wn*4 + nt*2 + (ctid>>1)
    float b4[2][4];
    #pragma unroll
    for (int nt = 0; nt < 2; nt++){
        int hid = wn*4 + nt*2 + (ctid >> 1);
        #pragma unroll
        for (int g = 0; g < 4; g++) b4[nt][g] = bias[g*H_ + j0 + hid];
    }
    float cst[2];
    cst[0] = 0.f; cst[1] = 0.f;

    float acc[2][4];                            // [nt][frag] = 8 floats
    int cstg = 0, cwrap = 0;

    auto zacc = [&](){
        #pragma unroll
        for (int nt = 0; nt < 2; nt++){ acc[nt][0]=0; acc[nt][1]=0; acc[nt][2]=0; acc[nt][3]=0; }
    };
    // process one 8KB chunk (A at abase) against weight chunk kc
    auto half_ = [&](uint32_t abase, uint32_t wsmem, int kc){
        uint32_t Ab = abase + arow;
        uint32_t Bb = wsmem + (uint32_t)kc*CHB + brow;
        #pragma unroll
        for (int kk2 = 0; kk2 < 128; kk2 += 32){
            uint32_t xt = ((uint32_t)kk2 + ac) ^ xorv;
            uint32_t a0,a1,a2,a3, c0,c1,c2,c3;
            ldsm4(a0,a1,a2,a3, Ab + xt);
            ldsm4(c0,c1,c2,c3, Bb + xt);
            mma16816(acc[0], a0,a1,a2,a3, c0, c2);
            mma16816(acc[1], a0,a1,a2,a3, c1, c3);
        }
    };
    // one stage = wait, 2 chunks, arrive
    auto stage2 = [&](uint32_t wsmem, int ka, int kb){
        mbar_wait(mb_full + cstg*8, (unsigned)(cwrap & 1));
        uint32_t abase = a_smem + (uint32_t)cstg*STGB;
        half_(abase,       wsmem, ka);
        half_(abase + CHB, wsmem, kb);
        if (lane == 0) mbar_arrive(mb_emp + cstg*8);
        if (++cstg == NSTG){ cstg = 0; cwrap++; }
    };

    // prologue: x-part of t=0
    zacc();
    stage2(wx_smem, 0, 1);
    stage2(wx_smem, 2, 3);

    for (int t = 0; t < S_; t++){
        // h-part: 8 stages, rotated chunk pairs
        for (int i = 0; i < 8; i++){
            int ca = (r0 + 2*i) & 15;
            stage2(wh_smem, ca, ca + 1);
        }

        // epilogue: all 32 lanes active (even lane -> row gid, odd -> gid+8)
        char* dst = g_h[(t + 1) & 1][bh] + (jgrp >> 2)*CHB;
        #pragma unroll
        for (int nt = 0; nt < 2; nt++){
            float v0 = acc[nt][0], v1 = acc[nt][1];
            float v2 = acc[nt][2], v3 = acc[nt][3];
            float p0 = __shfl_xor_sync(0xffffffffu, v0, 1);
            float p1 = __shfl_xor_sync(0xffffffffu, v1, 1);
            float p2 = __shfl_xor_sync(0xffffffffu, v2, 1);
            float p3 = __shfl_xor_sync(0xffffffffu, v3, 1);
            float f  = odd ? p2 : v0;
            float ii = odd ? p3 : v1;
            float gg = odd ? v2 : p0;
            float oo = odd ? v3 : p1;
            float fg = sigm_(f  + b4[nt][0]);
            float ig = sigm_(ii + b4[nt][1]);
            float gv = tanh_(gg + b4[nt][2]);
            float ov = sigm_(oo + b4[nt][3]);
            float cn = fg*cst[nt] + ig*gv;
            cst[nt] = cn;
            unsigned mine = (unsigned)__half_as_ushort(__float2half(ov * tanh_(cn)));
            unsigned part = __shfl_xor_sync(0xffffffffu, mine, 2);
            if (ctid < 2){
                unsigned packed = mine | (part << 16);   // hid pair (lo, hi)
                int r = wm*16 + gid + (odd << 3);
                int cb = (jgrp & 3)*32 + wn*8 + nt*4;
                *(uint32_t*)(dst + swz(r*128 + cb)) = packed;
            }
        }
        __syncwarp();                    // intra-warp HB
        if (lane == 0)
            asm volatile("red.release.gpu.global.add.u32 [%0], %1;\n"
                         :: "l"(&g_cnt[bh]), "r"(1u) : "memory");

        // x-part of t+1 in the barrier shadow
        if (t + 1 < S_){
            zacc();
            stage2(wx_smem, 0, 1);
            stage2(wx_smem, 2, 3);
        }
    }
}

// ---------------- final FC: out = h_T @ Wfc + bfc (fp32) -------------------
__global__ __launch_bounds__(256) void fc_kernel(const float* __restrict__ Wfc,
                                                 const float* __restrict__ bfc,
                                                 float* __restrict__ out){
    __shared__ float hsm[H_];
    int b = blockIdx.x, o = threadIdx.x;
    int bh = b >> 6, row = b & 63;
    for (int k = o; k < H_; k += 256){
        const char* chunk = g_h[0][bh] + (k >> 6)*CHB;   // S even -> buf 0
        hsm[k] = __half2float(*(const __half*)(chunk + swz(row*128 + (k & 63)*2)));
    }
    __syncthreads();
    float s = bfc[o];
    #pragma unroll 8
    for (int k = 0; k < H_; k++) s = fmaf(hsm[k], Wfc[(size_t)k*OUT_ + o], s);
    out[(size_t)b*OUT_ + o] = s;
}

// ---------------- entry -----------------------------------------------------
extern "C" void kernel_launch(void* const* d_in, const int* in_sizes, int n_in,
                              void* d_out, int out_size){
    (void)in_sizes; (void)n_in; (void)out_size;
    const float* x   = (const float*)d_in[0];
    const float* Wx  = (const float*)d_in[1];
    const float* Wh  = (const float*)d_in[2];
    const float* b   = (const float*)d_in[3];
    const float* Wfc = (const float*)d_in[4];
    const float* bfc = (const float*)d_in[5];
    float* out = (float*)d_out;

    cudaFuncSetAttribute(lstm_rec_kernel, cudaFuncAttributeMaxDynamicSharedMemorySize, SMEM_REC);

    conv_x_kernel<<<2048, 256>>>(x);
    conv_w_kernel<<<1024, 256>>>(Wx, Wh);
    zero_h_kernel<<<256, 256>>>();
    lstm_rec_kernel<<<NC_, 544, SMEM_REC>>>(b);
    fc_kernel<<<B_, 256>>>(Wfc, bfc, out);
}

// round 16
// speedup vs baseline: 1.1171x; 1.1171x over previous
#include <cuda_runtime.h>
#include <cuda_fp16.h>
#include <cstdint>
#include <cstddef>

#define B_   128
#define S_   1024
#define IN_  256
#define H_   1024
#define G4_  4096
#define OUT_ 256
#define NC_  128     // CTAs (1/SM): (bh 2) x (jgrp 64)
#define GRP_ 64      // CTAs per batch-half group
#define ARR_ (GRP_*8)// warp arrivals per group per step (512)
#define NSTG 4       // A pipeline stages (16KB each = 2 chunks)
#define CHB  8192    // chunk: 64 rows x 64 cols fp16, SW128 image
#define STGB 16384   // stage bytes (2 chunks)

// ---------------- device globals -------------------------------------------
__device__ __align__(1024) char g_x [(size_t)S_*2*4*CHB];   // 64 MB
__device__ __align__(1024) char g_h [2][2][16*CHB];          // 512 KB
__device__ __align__(16)  __half g_WxT[(size_t)G4_*IN_];     // [n][k]
__device__ __align__(16)  __half g_WhT[(size_t)G4_*H_];      // [n][k]
__device__ unsigned g_cnt[2];       // per-group warp-arrival counters

__device__ __host__ __forceinline__ int swz(int o){ return o ^ ((o >> 3) & 0x70); }

// ---------------- helpers ---------------------------------------------------
__device__ __forceinline__ void cp16(void* smem, const void* gmem){
    unsigned s = (unsigned)__cvta_generic_to_shared(smem);
    asm volatile("cp.async.cg.shared.global [%0], [%1], 16;\n" :: "r"(s), "l"(gmem));
}
__device__ __forceinline__ void cp_commit(){ asm volatile("cp.async.commit_group;\n"); }
template<int N> __device__ __forceinline__ void cp_wait(){ asm volatile("cp.async.wait_group %0;\n" :: "n"(N)); }

__device__ __forceinline__ void mbar_init(uint32_t mbar, uint32_t cnt){
    asm volatile("mbarrier.init.shared.b64 [%0], %1;\n" :: "r"(mbar), "r"(cnt) : "memory");
}
__device__ __forceinline__ void mbar_expect_tx(uint32_t mbar, uint32_t tx){
    asm volatile("mbarrier.arrive.expect_tx.shared.b64 _, [%0], %1;\n" :: "r"(mbar), "r"(tx) : "memory");
}
__device__ __forceinline__ void mbar_arrive(uint32_t mbar){
    asm volatile("mbarrier.arrive.shared.b64 _, [%0];\n" :: "r"(mbar) : "memory");
}
__device__ __forceinline__ void bulk_g2s(uint32_t sdst, const void* gsrc, uint32_t bytes, uint32_t mbar){
    asm volatile("cp.async.bulk.shared::cluster.global.mbarrier::complete_tx::bytes [%0], [%1], %2, [%3];\n"
                 :: "r"(sdst), "l"(gsrc), "r"(bytes), "r"(mbar) : "memory");
}
__device__ __forceinline__ void mbar_wait(uint32_t mbar, uint32_t parity){
    asm volatile(
        "{\n\t.reg .pred P1;\n\t"
        "LAB_W_%=:\n\t"
        "mbarrier.try_wait.parity.acquire.cta.shared::cta.b64 P1, [%0], %1;\n\t"
        "@P1 bra LAB_D_%=;\n\t"
        "bra LAB_W_%=;\n\t"
        "LAB_D_%=:\n\t}"
        :: "r"(mbar), "r"(parity) : "memory");
}
__device__ __forceinline__ void mma16816(float* c, uint32_t a0, uint32_t a1, uint32_t a2, uint32_t a3,
                                         uint32_t b0, uint32_t b1){
    asm volatile(
        "mma.sync.aligned.m16n8k16.row.col.f32.f16.f16.f32 "
        "{%0,%1,%2,%3}, {%4,%5,%6,%7}, {%8,%9}, {%0,%1,%2,%3};\n"
        : "+f"(c[0]), "+f"(c[1]), "+f"(c[2]), "+f"(c[3])
        : "r"(a0), "r"(a1), "r"(a2), "r"(a3), "r"(b0), "r"(b1));
}
__device__ __forceinline__ void ldsm4(uint32_t& r0, uint32_t& r1, uint32_t& r2, uint32_t& r3, uint32_t addr){
    asm volatile("ldmatrix.sync.aligned.m8n8.x4.shared.b16 {%0,%1,%2,%3}, [%4];\n"
                 : "=r"(r0), "=r"(r1), "=r"(r2), "=r"(r3) : "r"(addr));
}
__device__ __forceinline__ float sigm_(float x){ return 1.f / (1.f + __expf(-x)); }
__device__ __forceinline__ float tanh_(float x){ return 2.f / (1.f + __expf(-2.f*x)) - 1.f; }

// ---------------- phase 0: converts ----------------------------------------
__global__ void conv_x_kernel(const float* __restrict__ x){
    size_t n = (size_t)B_*S_*IN_;
    for (size_t i = (size_t)blockIdx.x*blockDim.x + threadIdx.x; i < n; i += (size_t)gridDim.x*blockDim.x){
        int k  = (int)(i % IN_);
        size_t bs = i / IN_;
        int s  = (int)(bs % S_);
        int b  = (int)(bs / S_);
        int bh = b >> 6, row = b & 63;
        char* chunk = g_x + (((size_t)s*2 + bh)*4 + (k >> 6))*CHB;
        *(__half*)(chunk + swz(row*128 + (k & 63)*2)) = __float2half(x[i]);
    }
}
__global__ void conv_w_kernel(const float* __restrict__ Wx, const float* __restrict__ Wh){
    size_t n1 = (size_t)G4_*IN_, n2 = (size_t)G4_*H_;
    for (size_t i = (size_t)blockIdx.x*blockDim.x + threadIdx.x; i < n1 + n2; i += (size_t)gridDim.x*blockDim.x){
        if (i < n1){
            int n = (int)(i / IN_), k = (int)(i % IN_);
            g_WxT[i] = __float2half(Wx[(size_t)k*G4_ + n]);
        } else {
            size_t j = i - n1;
            int n = (int)(j / H_), k = (int)(j % H_);
            g_WhT[j] = __float2half(Wh[(size_t)k*G4_ + n]);
        }
    }
}
__global__ void zero_h_kernel(){
    size_t n = sizeof(g_h)/4;
    unsigned* p = (unsigned*)g_h;
    for (size_t i = (size_t)blockIdx.x*blockDim.x + threadIdx.x; i < n; i += (size_t)gridDim.x*blockDim.x)
        p[i] = 0u;
    if (blockIdx.x == 0 && threadIdx.x < 2) g_cnt[threadIdx.x] = 0u;
}

// ---------------- recurrence ------------------------------------------------
// CTA (bh, jgrp): batch rows [bh*64,+64), hidden units [jgrp*16,+16) = 64 gate
// cols (col = hid*4+gate). 8 fully-decoupled compute warps (tile 32x16),
// ldmatrix-fed with SOFTWARE-PIPELINED double-buffered fragments (prefetch
// slice i+1 before mma of slice i). Producer warp streams 16KB bulk stages
// through a 4-stage mbarrier ring. No block syncs in the loop.
constexpr int A_OFF   = 0;
constexpr int WH_OFF  = NSTG*STGB;                // 65536
constexpr int WX_OFF  = WH_OFF + 16*CHB;          // 196608
constexpr int MB_OFF  = WX_OFF + 4*CHB;           // 229376
constexpr int SMEM_REC = MB_OFF + 2*NSTG*8 + 16;  // 229456

__global__ __launch_bounds__(288,1) void lstm_rec_kernel(const float* __restrict__ bias){
    extern __shared__ __align__(16) char sh[];
    int tid = threadIdx.x, lane = tid & 31, w = tid >> 5;
    int gid = lane >> 2, ctid = lane & 3;
    int bh = blockIdx.x & 1, jgrp = blockIdx.x >> 1;
    int j0 = jgrp * 16;
    int r0 = jgrp & 14;                         // rotated (even) h-chunk start

    uint32_t a_smem  = (uint32_t)__cvta_generic_to_shared(sh + A_OFF);
    uint32_t wh_smem = (uint32_t)__cvta_generic_to_shared(sh + WH_OFF);
    uint32_t wx_smem = (uint32_t)__cvta_generic_to_shared(sh + WX_OFF);
    uint32_t mb_full = (uint32_t)__cvta_generic_to_shared(sh + MB_OFF);   // +8*i
    uint32_t mb_emp  = mb_full + NSTG*8;                                  // +8*i
    char* Whs = sh + WH_OFF;
    char* Wxs = sh + WX_OFF;

    if (tid == 0){
        for (int i = 0; i < NSTG; i++){ mbar_init(mb_full + i*8, 1); mbar_init(mb_emp + i*8, 8); }
        asm volatile("fence.proxy.async.shared::cta;\n" ::: "memory");
    }
    // weight slices into swizzled chunk format (row n = hid*4+gate, 64 rows)
    for (int idx = tid; idx < 64*128; idx += 288){
        int n = idx >> 7, u = idx & 127;
        int hid = n >> 2, g = n & 3, k = u*8;
        cp16(Whs + (k >> 6)*CHB + swz(n*128 + (k & 63)*2),
             g_WhT + ((size_t)(g*H_ + j0 + hid))*H_ + k);
    }
    for (int idx = tid; idx < 64*32; idx += 288){
        int n = idx >> 5, u = idx & 31;
        int hid = n >> 2, g = n & 3, k = u*8;
        cp16(Wxs + (k >> 6)*CHB + swz(n*128 + (k & 63)*2),
             g_WxT + ((size_t)(g*H_ + j0 + hid))*IN_ + k);
    }
    cp_commit(); cp_wait<0>();
    __syncthreads();   // the ONLY full-block sync

    if (w == 8){
        // ----------------- producer warp (lane 0 only) -----------------
        if (lane == 0){
            int pst = 0, pwrap = 0;
            auto issue = [&](const char* src){
                if (pwrap > 0) mbar_wait(mb_emp + pst*8, (unsigned)((pwrap - 1) & 1));
                mbar_expect_tx(mb_full + pst*8, STGB);
                bulk_g2s(a_smem + pst*STGB, src, STGB, mb_full + pst*8);
                if (++pst == NSTG){ pst = 0; pwrap++; }
            };
            // x of t=0: 2 stages (32KB contiguous)
            issue(g_x + ((size_t)bh)*4*CHB);
            issue(g_x + ((size_t)bh)*4*CHB + STGB);
            for (int t = 0; t < S_; t++){
                if (t > 0){
                    unsigned v, tgtv = (unsigned)t * ARR_;
                    do { asm volatile("ld.acquire.gpu.global.u32 %0, [%1];\n" : "=r"(v) : "l"(&g_cnt[bh]) : "memory"); }
                    while (v < tgtv);
                }
                // h: 8 stages of 2 chunks, rotated even-aligned pairs (contiguous)
                for (int i = 0; i < 8; i++){
                    int ca = (r0 + 2*i) & 15;
                    issue(g_h[t & 1][bh] + ca*CHB);
                }
                if (t + 1 < S_){
                    const char* xb = g_x + (((size_t)(t+1)*2 + bh)*4)*CHB;
                    issue(xb);
                    issue(xb + STGB);
                }
            }
        }
        return;
    }

    // ----------------- compute warps (w = 0..7, fully decoupled) -----------
    int wm = w >> 2, wn = w & 3;               // warp tile: rows wm*32+, cols wn*16+

    // ldmatrix per-lane geometry
    int mat = lane >> 3, rin = lane & 7;
    uint32_t xorv = (uint32_t)(rin << 4);
    uint32_t ac   = (uint32_t)((mat >> 1) << 4);
    uint32_t arow0 = (uint32_t)((wm*32 +  0 + (mat & 1)*8 + rin) * 128);
    uint32_t arow1 = (uint32_t)((wm*32 + 16 + (mat & 1)*8 + rin) * 128);
    uint32_t brow  = (uint32_t)((wn*16 +      (mat & 1)*8 + rin) * 128);

    int odd = ctid & 1;
    float b4[2][4];
    #pragma unroll
    for (int nt = 0; nt < 2; nt++){
        int hid = wn*4 + nt*2 + (ctid >> 1);
        #pragma unroll
        for (int g = 0; g < 4; g++) b4[nt][g] = bias[g*H_ + j0 + hid];
    }
    float cst[2][2];
    cst[0][0]=0.f; cst[0][1]=0.f; cst[1][0]=0.f; cst[1][1]=0.f;

    float acc[2][2][4];
    int cstg = 0, cwrap = 0;

    auto zacc = [&](){
        #pragma unroll
        for (int mt = 0; mt < 2; mt++)
            #pragma unroll
            for (int nt = 0; nt < 2; nt++){ acc[mt][nt][0]=0; acc[mt][nt][1]=0; acc[mt][nt][2]=0; acc[mt][nt][3]=0; }
    };

    // one stage = wait, 8 software-pipelined slices (2 chunks x 4 kk), arrive
    // fragments double-buffered: prefetch slice s+1 before mma of slice s.
    uint32_t fr[2][12];   // [buf][a0..a3, e0..e3, c0..c3]
    auto stage2 = [&](uint32_t wsmem, int ka, int kb){
        mbar_wait(mb_full + cstg*8, (unsigned)(cwrap & 1));
        uint32_t abase = a_smem + (uint32_t)cstg*STGB;
        uint32_t bA = wsmem + (uint32_t)ka*CHB + brow;
        uint32_t bB = wsmem + (uint32_t)kb*CHB + brow;
        // slice s: chunk = s>>2, kk2 = (s&3)*32
        #define LOADSL(buf, s) do{ \
            uint32_t ab_ = abase + ((s) >> 2)*CHB; \
            uint32_t bb_ = ((s) < 4) ? bA : bB; \
            uint32_t xt_ = ((uint32_t)(((s) & 3)*32) + ac) ^ xorv; \
            ldsm4(fr[buf][0], fr[buf][1], fr[buf][2],  fr[buf][3],  ab_ + arow0 + xt_); \
            ldsm4(fr[buf][4], fr[buf][5], fr[buf][6],  fr[buf][7],  ab_ + arow1 + xt_); \
            ldsm4(fr[buf][8], fr[buf][9], fr[buf][10], fr[buf][11], bb_ + xt_); \
        }while(0)
        #define MMASL(buf) do{ \
            mma16816(acc[0][0], fr[buf][0], fr[buf][1], fr[buf][2], fr[buf][3], fr[buf][8],  fr[buf][10]); \
            mma16816(acc[0][1], fr[buf][0], fr[buf][1], fr[buf][2], fr[buf][3], fr[buf][9],  fr[buf][11]); \
            mma16816(acc[1][0], fr[buf][4], fr[buf][5], fr[buf][6], fr[buf][7], fr[buf][8],  fr[buf][10]); \
            mma16816(acc[1][1], fr[buf][4], fr[buf][5], fr[buf][6], fr[buf][7], fr[buf][9],  fr[buf][11]); \
        }while(0)
        LOADSL(0, 0);
        #pragma unroll
        for (int s = 0; s < 8; s++){
            if (s < 7) LOADSL((s + 1) & 1, s + 1);
            MMASL(s & 1);
        }
        #undef LOADSL
        #undef MMASL
        if (lane == 0) mbar_arrive(mb_emp + cstg*8);
        if (++cstg == NSTG){ cstg = 0; cwrap++; }
    };

    // prologue: x-part of t=0
    zacc();
    stage2(wx_smem, 0, 1);
    stage2(wx_smem, 2, 3);

    for (int t = 0; t < S_; t++){
        // h-part: 8 stages, rotated chunk pairs
        for (int i = 0; i < 8; i++){
            int ca = (r0 + 2*i) & 15;
            stage2(wh_smem, ca, ca + 1);
        }

        // epilogue: all 32 lanes active (even lane -> row gid, odd -> gid+8)
        char* dst = g_h[(t + 1) & 1][bh] + (jgrp >> 2)*CHB;
        #pragma unroll
        for (int mt = 0; mt < 2; mt++){
            #pragma unroll
            for (int nt = 0; nt < 2; nt++){
                float v0 = acc[mt][nt][0], v1 = acc[mt][nt][1];
                float v2 = acc[mt][nt][2], v3 = acc[mt][nt][3];
                float p0 = __shfl_xor_sync(0xffffffffu, v0, 1);
                float p1 = __shfl_xor_sync(0xffffffffu, v1, 1);
                float p2 = __shfl_xor_sync(0xffffffffu, v2, 1);
                float p3 = __shfl_xor_sync(0xffffffffu, v3, 1);
                float f  = odd ? p2 : v0;
                float ii = odd ? p3 : v1;
                float gg = odd ? v2 : p0;
                float oo = odd ? v3 : p1;
                float fg = sigm_(f  + b4[nt][0]);
                float ig = sigm_(ii + b4[nt][1]);
                float gv = tanh_(gg + b4[nt][2]);
                float ov = sigm_(oo + b4[nt][3]);
                float cn = fg*cst[mt][nt] + ig*gv;
                cst[mt][nt] = cn;
                unsigned mine = (unsigned)__half_as_ushort(__float2half(ov * tanh_(cn)));
                unsigned part = __shfl_xor_sync(0xffffffffu, mine, 2);
                if (ctid < 2){
                    unsigned packed = mine | (part << 16);   // hid pair (lo, hi)
                    int r = wm*32 + mt*16 + gid + (odd << 3);
                    int cb = (jgrp & 3)*32 + wn*8 + nt*4;
                    *(uint32_t*)(dst + swz(r*128 + cb)) = packed;
                }
            }
        }
        __syncwarp();                    // intra-warp HB
        if (lane == 0)
            asm volatile("red.release.gpu.global.add.u32 [%0], %1;\n"
                         :: "l"(&g_cnt[bh]), "r"(1u) : "memory");

        // x-part of t+1 in the barrier shadow
        if (t + 1 < S_){
            zacc();
            stage2(wx_smem, 0, 1);
            stage2(wx_smem, 2, 3);
        }
    }
}

// ---------------- final FC: out = h_T @ Wfc + bfc (fp32) -------------------
__global__ __launch_bounds__(256) void fc_kernel(const float* __restrict__ Wfc,
                                                 const float* __restrict__ bfc,
                                                 float* __restrict__ out){
    __shared__ float hsm[H_];
    int b = blockIdx.x, o = threadIdx.x;
    int bh = b >> 6, row = b & 63;
    for (int k = o; k < H_; k += 256){
        const char* chunk = g_h[0][bh] + (k >> 6)*CHB;   // S even -> buf 0
        hsm[k] = __half2float(*(const __half*)(chunk + swz(row*128 + (k & 63)*2)));
    }
    __syncthreads();
    float s = bfc[o];
    #pragma unroll 8
    for (int k = 0; k < H_; k++) s = fmaf(hsm[k], Wfc[(size_t)k*OUT_ + o], s);
    out[(size_t)b*OUT_ + o] = s;
}

// ---------------- entry -----------------------------------------------------
extern "C" void kernel_launch(void* const* d_in, const int* in_sizes, int n_in,
                              void* d_out, int out_size){
    (void)in_sizes; (void)n_in; (void)out_size;
    const float* x   = (const float*)d_in[0];
    const float* Wx  = (const float*)d_in[1];
    const float* Wh  = (const float*)d_in[2];
    const float* b   = (const float*)d_in[3];
    const float* Wfc = (const float*)d_in[4];
    const float* bfc = (const float*)d_in[5];
    float* out = (float*)d_out;

    cudaFuncSetAttribute(lstm_rec_kernel, cudaFuncAttributeMaxDynamicSharedMemorySize, SMEM_REC);

    conv_x_kernel<<<2048, 256>>>(x);
    conv_w_kernel<<<1024, 256>>>(Wx, Wh);
    zero_h_kernel<<<256, 256>>>();
    lstm_rec_kernel<<<NC_, 288, SMEM_REC>>>(b);
    fc_kernel<<<B_, 256>>>(Wfc, bfc, out);
}

// round 17
// speedup vs baseline: 1.1512x; 1.0305x over previous
#include <cuda_runtime.h>
#include <cuda_fp16.h>
#include <cstdint>
#include <cstddef>

#define B_   128
#define S_   1024
#define IN_  256
#define H_   1024
#define G4_  4096
#define OUT_ 256
#define NC_  128     // CTAs (1/SM): (bh 2) x (jgrp 64)
#define GRP_ 64      // CTAs per batch-half group
#define PARR 64      // warp arrivals per PAIR per step (8 CTAs x 8 warps)
#define NSTG 4       // A pipeline stages (16KB each = 2 chunks)
#define CHB  8192    // chunk: 64 rows x 64 cols fp16, SW128 image
#define STGB 16384   // stage bytes (2 chunks)

// ---------------- device globals -------------------------------------------
__device__ __align__(1024) char g_x [(size_t)S_*2*4*CHB];   // 64 MB
__device__ __align__(1024) char g_h [2][2][16*CHB];          // 512 KB
__device__ __align__(16)  __half g_WxT[(size_t)G4_*IN_];     // [n][k]
__device__ __align__(16)  __half g_WhT[(size_t)G4_*H_];      // [n][k]
__device__ __align__(32) unsigned g_cntA[2][8];  // per-(group, chunk-pair) counters

__device__ __host__ __forceinline__ int swz(int o){ return o ^ ((o >> 3) & 0x70); }

// ---------------- helpers ---------------------------------------------------
__device__ __forceinline__ void cp16(void* smem, const void* gmem){
    unsigned s = (unsigned)__cvta_generic_to_shared(smem);
    asm volatile("cp.async.cg.shared.global [%0], [%1], 16;\n" :: "r"(s), "l"(gmem));
}
__device__ __forceinline__ void cp_commit(){ asm volatile("cp.async.commit_group;\n"); }
template<int N> __device__ __forceinline__ void cp_wait(){ asm volatile("cp.async.wait_group %0;\n" :: "n"(N)); }

__device__ __forceinline__ void mbar_init(uint32_t mbar, uint32_t cnt){
    asm volatile("mbarrier.init.shared.b64 [%0], %1;\n" :: "r"(mbar), "r"(cnt) : "memory");
}
__device__ __forceinline__ void mbar_expect_tx(uint32_t mbar, uint32_t tx){
    asm volatile("mbarrier.arrive.expect_tx.shared.b64 _, [%0], %1;\n" :: "r"(mbar), "r"(tx) : "memory");
}
__device__ __forceinline__ void mbar_arrive(uint32_t mbar){
    asm volatile("mbarrier.arrive.shared.b64 _, [%0];\n" :: "r"(mbar) : "memory");
}
__device__ __forceinline__ void bulk_g2s(uint32_t sdst, const void* gsrc, uint32_t bytes, uint32_t mbar){
    asm volatile("cp.async.bulk.shared::cluster.global.mbarrier::complete_tx::bytes [%0], [%1], %2, [%3];\n"
                 :: "r"(sdst), "l"(gsrc), "r"(bytes), "r"(mbar) : "memory");
}
__device__ __forceinline__ void mbar_wait(uint32_t mbar, uint32_t parity){
    asm volatile(
        "{\n\t.reg .pred P1;\n\t"
        "LAB_W_%=:\n\t"
        "mbarrier.try_wait.parity.acquire.cta.shared::cta.b64 P1, [%0], %1;\n\t"
        "@P1 bra LAB_D_%=;\n\t"
        "bra LAB_W_%=;\n\t"
        "LAB_D_%=:\n\t}"
        :: "r"(mbar), "r"(parity) : "memory");
}
__device__ __forceinline__ void mma16816(float* c, uint32_t a0, uint32_t a1, uint32_t a2, uint32_t a3,
                                         uint32_t b0, uint32_t b1){
    asm volatile(
        "mma.sync.aligned.m16n8k16.row.col.f32.f16.f16.f32 "
        "{%0,%1,%2,%3}, {%4,%5,%6,%7}, {%8,%9}, {%0,%1,%2,%3};\n"
        : "+f"(c[0]), "+f"(c[1]), "+f"(c[2]), "+f"(c[3])
        : "r"(a0), "r"(a1), "r"(a2), "r"(a3), "r"(b0), "r"(b1));
}
__device__ __forceinline__ void ldsm4(uint32_t& r0, uint32_t& r1, uint32_t& r2, uint32_t& r3, uint32_t addr){
    asm volatile("ldmatrix.sync.aligned.m8n8.x4.shared.b16 {%0,%1,%2,%3}, [%4];\n"
                 : "=r"(r0), "=r"(r1), "=r"(r2), "=r"(r3) : "r"(addr));
}
__device__ __forceinline__ void ld_cnt4(const unsigned* p, unsigned& a, unsigned& b, unsigned& c, unsigned& d){
    asm volatile("ld.acquire.gpu.global.v4.u32 {%0,%1,%2,%3}, [%4];\n"
                 : "=r"(a), "=r"(b), "=r"(c), "=r"(d) : "l"(p) : "memory");
}
__device__ __forceinline__ float sigm_(float x){ return 1.f / (1.f + __expf(-x)); }
__device__ __forceinline__ float tanh_(float x){ return 2.f / (1.f + __expf(-2.f*x)) - 1.f; }

// ---------------- phase 0: converts ----------------------------------------
__global__ void conv_x_kernel(const float* __restrict__ x){
    size_t n = (size_t)B_*S_*IN_;
    for (size_t i = (size_t)blockIdx.x*blockDim.x + threadIdx.x; i < n; i += (size_t)gridDim.x*blockDim.x){
        int k  = (int)(i % IN_);
        size_t bs = i / IN_;
        int s  = (int)(bs % S_);
        int b  = (int)(bs / S_);
        int bh = b >> 6, row = b & 63;
        char* chunk = g_x + (((size_t)s*2 + bh)*4 + (k >> 6))*CHB;
        *(__half*)(chunk + swz(row*128 + (k & 63)*2)) = __float2half(x[i]);
    }
}
__global__ void conv_w_kernel(const float* __restrict__ Wx, const float* __restrict__ Wh){
    size_t n1 = (size_t)G4_*IN_, n2 = (size_t)G4_*H_;
    for (size_t i = (size_t)blockIdx.x*blockDim.x + threadIdx.x; i < n1 + n2; i += (size_t)gridDim.x*blockDim.x){
        if (i < n1){
            int n = (int)(i / IN_), k = (int)(i % IN_);
            g_WxT[i] = __float2half(Wx[(size_t)k*G4_ + n]);
        } else {
            size_t j = i - n1;
            int n = (int)(j / H_), k = (int)(j % H_);
            g_WhT[j] = __float2half(Wh[(size_t)k*G4_ + n]);
        }
    }
}
__global__ void zero_h_kernel(){
    size_t n = sizeof(g_h)/4;
    unsigned* p = (unsigned*)g_h;
    for (size_t i = (size_t)blockIdx.x*blockDim.x + threadIdx.x; i < n; i += (size_t)gridDim.x*blockDim.x)
        p[i] = 0u;
    if (blockIdx.x == 0 && threadIdx.x < 16) ((unsigned*)g_cntA)[threadIdx.x] = 0u;
}

// ---------------- recurrence ------------------------------------------------
// CTA (bh, jgrp): batch rows [bh*64,+64), hidden units [jgrp*16,+16) = 64 gate
// cols (col = hid*4+gate). 8 fully-decoupled compute warps (tile 32x16),
// ldmatrix-fed. Producer warp streams 16KB bulk stages through a 4-stage ring.
// PAIR-GRANULAR cross-CTA dependency: h-chunk pair p is written by 8 CTAs
// (jgrp>>3 == p); producer gates each h-stage on counter[p] >= t*64 using
// register-cached values refreshed by ld.acquire.v4 (4 counters per round trip).
constexpr int A_OFF   = 0;
constexpr int WH_OFF  = NSTG*STGB;                // 65536
constexpr int WX_OFF  = WH_OFF + 16*CHB;          // 196608
constexpr int MB_OFF  = WX_OFF + 4*CHB;           // 229376
constexpr int SMEM_REC = MB_OFF + 2*NSTG*8 + 16;  // 229456

__global__ __launch_bounds__(288,1) void lstm_rec_kernel(const float* __restrict__ bias){
    extern __shared__ __align__(16) char sh[];
    int tid = threadIdx.x, lane = tid & 31, w = tid >> 5;
    int gid = lane >> 2, ctid = lane & 3;
    int bh = blockIdx.x & 1, jgrp = blockIdx.x >> 1;
    int j0 = jgrp * 16;
    int r0 = jgrp & 14;                         // rotated (even) h-chunk start
    int p0 = r0 >> 1;                           // rotated pair start

    uint32_t a_smem  = (uint32_t)__cvta_generic_to_shared(sh + A_OFF);
    uint32_t wh_smem = (uint32_t)__cvta_generic_to_shared(sh + WH_OFF);
    uint32_t wx_smem = (uint32_t)__cvta_generic_to_shared(sh + WX_OFF);
    uint32_t mb_full = (uint32_t)__cvta_generic_to_shared(sh + MB_OFF);   // +8*i
    uint32_t mb_emp  = mb_full + NSTG*8;                                  // +8*i
    char* Whs = sh + WH_OFF;
    char* Wxs = sh + WX_OFF;

    if (tid == 0){
        for (int i = 0; i < NSTG; i++){ mbar_init(mb_full + i*8, 1); mbar_init(mb_emp + i*8, 8); }
        asm volatile("fence.proxy.async.shared::cta;\n" ::: "memory");
    }
    // weight slices into swizzled chunk format (row n = hid*4+gate, 64 rows)
    for (int idx = tid; idx < 64*128; idx += 288){
        int n = idx >> 7, u = idx & 127;
        int hid = n >> 2, g = n & 3, k = u*8;
        cp16(Whs + (k >> 6)*CHB + swz(n*128 + (k & 63)*2),
             g_WhT + ((size_t)(g*H_ + j0 + hid))*H_ + k);
    }
    for (int idx = tid; idx < 64*32; idx += 288){
        int n = idx >> 5, u = idx & 31;
        int hid = n >> 2, g = n & 3, k = u*8;
        cp16(Wxs + (k >> 6)*CHB + swz(n*128 + (k & 63)*2),
             g_WxT + ((size_t)(g*H_ + j0 + hid))*IN_ + k);
    }
    cp_commit(); cp_wait<0>();
    __syncthreads();   // the ONLY full-block sync

    if (w == 8){
        // ----------------- producer warp (lane 0 only) -----------------
        if (lane == 0){
            int pst = 0, pwrap = 0;
            unsigned s0 = 0, s1 = 0, s2 = 0, s3 = 0;     // cached counters 0..3
            unsigned s4 = 0, s5 = 0, s6 = 0, s7 = 0;     // cached counters 4..7
            const unsigned* cbase = &g_cntA[bh][0];
            auto seen = [&](int p) -> unsigned {
                switch (p){
                    case 0: return s0; case 1: return s1; case 2: return s2; case 3: return s3;
                    case 4: return s4; case 5: return s5; case 6: return s6; default: return s7;
                }
            };
            auto pollPair = [&](int p, unsigned tgt){
                while (seen(p) < tgt){
                    if (p < 4) ld_cnt4(cbase,     s0, s1, s2, s3);
                    else       ld_cnt4(cbase + 4, s4, s5, s6, s7);
                }
            };
            auto issue = [&](const char* src){
                if (pwrap > 0) mbar_wait(mb_emp + pst*8, (unsigned)((pwrap - 1) & 1));
                mbar_expect_tx(mb_full + pst*8, STGB);
                bulk_g2s(a_smem + pst*STGB, src, STGB, mb_full + pst*8);
                if (++pst == NSTG){ pst = 0; pwrap++; }
            };
            // x of t=0: 2 stages (32KB contiguous)
            issue(g_x + ((size_t)bh)*4*CHB);
            issue(g_x + ((size_t)bh)*4*CHB + STGB);
            for (int t = 0; t < S_; t++){
                unsigned tgt = (unsigned)t * PARR;
                // h: 8 stages = 8 chunk pairs, rotated; gate each on its pair counter
                for (int i = 0; i < 8; i++){
                    int p = (p0 + i) & 7;
                    if (t > 0) pollPair(p, tgt);
                    issue(g_h[t & 1][bh] + (p*2)*CHB);
                }
                if (t + 1 < S_){
                    const char* xb = g_x + (((size_t)(t+1)*2 + bh)*4)*CHB;
                    issue(xb);
                    issue(xb + STGB);
                }
            }
        }
        return;
    }

    // ----------------- compute warps (w = 0..7, fully decoupled) -----------
    int wm = w >> 2, wn = w & 3;               // warp tile: rows wm*32+, cols wn*16+

    // ldmatrix per-lane geometry
    int mat = lane >> 3, rin = lane & 7;
    uint32_t xorv = (uint32_t)(rin << 4);
    uint32_t ac   = (uint32_t)((mat >> 1) << 4);
    uint32_t arow0 = (uint32_t)((wm*32 +  0 + (mat & 1)*8 + rin) * 128);
    uint32_t arow1 = (uint32_t)((wm*32 + 16 + (mat & 1)*8 + rin) * 128);
    uint32_t brow  = (uint32_t)((wn*16 +      (mat & 1)*8 + rin) * 128);

    int odd = ctid & 1;
    float b4[2][4];
    #pragma unroll
    for (int nt = 0; nt < 2; nt++){
        int hid = wn*4 + nt*2 + (ctid >> 1);
        #pragma unroll
        for (int g = 0; g < 4; g++) b4[nt][g] = bias[g*H_ + j0 + hid];
    }
    float cst[2][2];
    cst[0][0]=0.f; cst[0][1]=0.f; cst[1][0]=0.f; cst[1][1]=0.f;

    float acc[2][2][4];
    int cstg = 0, cwrap = 0;
    unsigned* mycnt = &g_cntA[bh][jgrp >> 3];   // own pair counter

    auto zacc = [&](){
        #pragma unroll
        for (int mt = 0; mt < 2; mt++)
            #pragma unroll
            for (int nt = 0; nt < 2; nt++){ acc[mt][nt][0]=0; acc[mt][nt][1]=0; acc[mt][nt][2]=0; acc[mt][nt][3]=0; }
    };
    // process one 8KB chunk (A at abase) against weight chunk kc
    auto half_ = [&](uint32_t abase, uint32_t wsmem, int kc){
        uint32_t Ab0 = abase + arow0;
        uint32_t Ab1 = abase + arow1;
        uint32_t Bb  = wsmem + (uint32_t)kc*CHB + brow;
        #pragma unroll
        for (int kk2 = 0; kk2 < 128; kk2 += 32){
            uint32_t xt = ((uint32_t)kk2 + ac) ^ xorv;
            uint32_t a0,a1,a2,a3, e0,e1,e2,e3, c0,c1,c2,c3;
            ldsm4(a0,a1,a2,a3, Ab0 + xt);
            ldsm4(e0,e1,e2,e3, Ab1 + xt);
            ldsm4(c0,c1,c2,c3, Bb  + xt);
            mma16816(acc[0][0], a0,a1,a2,a3, c0, c2);
            mma16816(acc[0][1], a0,a1,a2,a3, c1, c3);
            mma16816(acc[1][0], e0,e1,e2,e3, c0, c2);
            mma16816(acc[1][1], e0,e1,e2,e3, c1, c3);
        }
    };
    // one stage = wait, 2 chunks, arrive
    auto stage2 = [&](uint32_t wsmem, int ka, int kb){
        mbar_wait(mb_full + cstg*8, (unsigned)(cwrap & 1));
        uint32_t abase = a_smem + (uint32_t)cstg*STGB;
        half_(abase,       wsmem, ka);
        half_(abase + CHB, wsmem, kb);
        if (lane == 0) mbar_arrive(mb_emp + cstg*8);
        if (++cstg == NSTG){ cstg = 0; cwrap++; }
    };

    // prologue: x-part of t=0
    zacc();
    stage2(wx_smem, 0, 1);
    stage2(wx_smem, 2, 3);

    for (int t = 0; t < S_; t++){
        // h-part: 8 stages, rotated chunk pairs
        for (int i = 0; i < 8; i++){
            int ca = (r0 + 2*i) & 15;
            stage2(wh_smem, ca, ca + 1);
        }

        // epilogue: all 32 lanes active (even lane -> row gid, odd -> gid+8)
        char* dst = g_h[(t + 1) & 1][bh] + (jgrp >> 2)*CHB;
        #pragma unroll
        for (int mt = 0; mt < 2; mt++){
            #pragma unroll
            for (int nt = 0; nt < 2; nt++){
                float v0 = acc[mt][nt][0], v1 = acc[mt][nt][1];
                float v2 = acc[mt][nt][2], v3 = acc[mt][nt][3];
                float p0v = __shfl_xor_sync(0xffffffffu, v0, 1);
                float p1v = __shfl_xor_sync(0xffffffffu, v1, 1);
                float p2v = __shfl_xor_sync(0xffffffffu, v2, 1);
                float p3v = __shfl_xor_sync(0xffffffffu, v3, 1);
                float f  = odd ? p2v : v0;
                float ii = odd ? p3v : v1;
                float gg = odd ? v2 : p0v;
                float oo = odd ? v3 : p1v;
                float fg = sigm_(f  + b4[nt][0]);
                float ig = sigm_(ii + b4[nt][1]);
                float gv = tanh_(gg + b4[nt][2]);
                float ov = sigm_(oo + b4[nt][3]);
                float cn = fg*cst[mt][nt] + ig*gv;
                cst[mt][nt] = cn;
                unsigned mine = (unsigned)__half_as_ushort(__float2half(ov * tanh_(cn)));
                unsigned part = __shfl_xor_sync(0xffffffffu, mine, 2);
                if (ctid < 2){
                    unsigned packed = mine | (part << 16);   // hid pair (lo, hi)
                    int r = wm*32 + mt*16 + gid + (odd << 3);
                    int cb = (jgrp & 3)*32 + wn*8 + nt*4;
                    *(uint32_t*)(dst + swz(r*128 + cb)) = packed;
                }
            }
        }
        __syncwarp();                    // intra-warp HB
        if (lane == 0)
            asm volatile("red.release.gpu.global.add.u32 [%0], %1;\n"
                         :: "l"(mycnt), "r"(1u) : "memory");

        // x-part of t+1 in the barrier shadow
        if (t + 1 < S_){
            zacc();
            stage2(wx_smem, 0, 1);
            stage2(wx_smem, 2, 3);
        }
    }
}

// ---------------- final FC: out = h_T @ Wfc + bfc (fp32) -------------------
__global__ __launch_bounds__(256) void fc_kernel(const float* __restrict__ Wfc,
                                                 const float* __restrict__ bfc,
                                                 float* __restrict__ out){
    __shared__ float hsm[H_];
    int b = blockIdx.x, o = threadIdx.x;
    int bh = b >> 6, row = b & 63;
    for (int k = o; k < H_; k += 256){
        const char* chunk = g_h[0][bh] + (k >> 6)*CHB;   // S even -> buf 0
        hsm[k] = __half2float(*(const __half*)(chunk + swz(row*128 + (k & 63)*2)));
    }
    __syncthreads();
    float s = bfc[o];
    #pragma unroll 8
    for (int k = 0; k < H_; k++) s = fmaf(hsm[k], Wfc[(size_t)k*OUT_ + o], s);
    out[(size_t)b*OUT_ + o] = s;
}

// ---------------- entry -----------------------------------------------------
extern "C" void kernel_launch(void* const* d_in, const int* in_sizes, int n_in,
                              void* d_out, int out_size){
    (void)in_sizes; (void)n_in; (void)out_size;
    const float* x   = (const float*)d_in[0];
    const float* Wx  = (const float*)d_in[1];
    const float* Wh  = (const float*)d_in[2];
    const float* b   = (const float*)d_in[3];
    const float* Wfc = (const float*)d_in[4];
    const float* bfc = (const float*)d_in[5];
    float* out = (float*)d_out;

    cudaFuncSetAttribute(lstm_rec_kernel, cudaFuncAttributeMaxDynamicSharedMemorySize, SMEM_REC);

    conv_x_kernel<<<2048, 256>>>(x);
    conv_w_kernel<<<1024, 256>>>(Wx, Wh);
    zero_h_kernel<<<256, 256>>>();
    lstm_rec_kernel<<<NC_, 288, SMEM_REC>>>(b);
    fc_kernel<<<B_, 256>>>(Wfc, bfc, out);
}